// round 8
// baseline (speedup 1.0000x reference)
#include <cuda_runtime.h>
#include <cuda_fp16.h>
#include <cstdint>

#define K_DIM 1024
#define O_DIM 1024
#define FP8_MAX_F 448.0f

// ---- GEMM tiling (HMMA mma.sync path; tcgen05 unavailable at compute_103) ----
#define BM 128
#define BN 256
#define BK 64                  // 128 bytes/row fp16 = one SW128 atom
#define STAGES 4
#define NT (K_DIM / BK)        // 16

#define A_STAGE_BYTES (BM * 128)                        // 16384
#define B_STAGE_BYTES (BN * 128)                        // 32768
#define STAGE_BYTES   (A_STAGE_BYTES + B_STAGE_BYTES)   // 49152
#define SMEM_TOTAL    (STAGES * STAGE_BYTES)            // 196608

static __device__ __forceinline__ uint32_t sw128(uint32_t off) {
    return off ^ ((off >> 3) & 0x70);
}
static __device__ __forceinline__ uint32_t smem_u32(const void* p) {
    uint32_t a;
    asm("{ .reg .u64 t; cvta.to.shared.u64 t, %1; cvt.u32.u64 %0, t; }" : "=r"(a) : "l"(p));
    return a;
}

// ---- scratch (static device globals; no runtime allocation) ----
__device__ unsigned int g_amax_bits;
__device__ float  g_wscale[O_DIM];
__device__ __half g_wq[(size_t)O_DIM * K_DIM];
__device__ __half g_xq[(size_t)32768 * K_DIM];

// ---------------- kernel 0: reset ----------------
__global__ void reset_kernel() { g_amax_bits = 0u; }

// ---------------- kernel 1: global amax of x ----------------
__global__ void amax_kernel(const float* __restrict__ x, int n4) {
    const float4* x4 = (const float4*)x;
    float m = 0.f;
    int stride = gridDim.x * blockDim.x;
    for (int j = blockIdx.x * blockDim.x + threadIdx.x; j < n4; j += stride) {
        float4 v = x4[j];
        m = fmaxf(m, fmaxf(fmaxf(fabsf(v.x), fabsf(v.y)), fmaxf(fabsf(v.z), fabsf(v.w))));
    }
    #pragma unroll
    for (int o = 16; o; o >>= 1) m = fmaxf(m, __shfl_xor_sync(0xffffffffu, m, o));
    __shared__ float sm[8];
    if ((threadIdx.x & 31) == 0) sm[threadIdx.x >> 5] = m;
    __syncthreads();
    if (threadIdx.x < 32) {
        m = (threadIdx.x < (blockDim.x >> 5)) ? sm[threadIdx.x] : 0.f;
        #pragma unroll
        for (int o = 4; o; o >>= 1) m = fmaxf(m, __shfl_xor_sync(0xffffffffu, m, o));
        if (threadIdx.x == 0) atomicMax(&g_amax_bits, __float_as_uint(m));
    }
}

// ---------------- kernel 2: per-row weight amax + quantize to fp16 ----------------
__global__ void wq_kernel(const float* __restrict__ w) {
    int row = blockIdx.x;
    const float* wr = w + (size_t)row * K_DIM;
    float m = 0.f;
    for (int k = threadIdx.x; k < K_DIM; k += 128) m = fmaxf(m, fabsf(wr[k]));
    #pragma unroll
    for (int o = 16; o; o >>= 1) m = fmaxf(m, __shfl_xor_sync(0xffffffffu, m, o));
    __shared__ float sm[4];
    if ((threadIdx.x & 31) == 0) sm[threadIdx.x >> 5] = m;
    __syncthreads();
    float am = fmaxf(fmaxf(sm[0], sm[1]), fmaxf(sm[2], sm[3]));
    float scale = fmaxf(__fdiv_rn(am, FP8_MAX_F), 1e-12f);
    if (threadIdx.x == 0) g_wscale[row] = scale;
    for (int k = threadIdx.x; k < K_DIM; k += 128) {
        float q = rintf(fminf(fmaxf(__fdiv_rn(wr[k], scale), -FP8_MAX_F), FP8_MAX_F));
        g_wq[(size_t)row * K_DIM + k] = __float2half_rn(q);  // exact (integer <= 448)
    }
}

// ---------------- kernel 3: quantize x to fp16 (2x float4 per iter for MLP) ----------------
__global__ void xq_kernel(const float* __restrict__ x, int n8) {
    float scale = fmaxf(__fdiv_rn(__uint_as_float(g_amax_bits), FP8_MAX_F), 1e-12f);
    const float4* x4 = (const float4*)x;
    int stride = gridDim.x * blockDim.x;
    for (int j = blockIdx.x * blockDim.x + threadIdx.x; j < n8; j += stride) {
        float4 v0 = x4[j * 2];
        float4 v1 = x4[j * 2 + 1];
        float q[8];
        q[0] = v0.x; q[1] = v0.y; q[2] = v0.z; q[3] = v0.w;
        q[4] = v1.x; q[5] = v1.y; q[6] = v1.z; q[7] = v1.w;
        uint4 u;
        uint32_t* up = (uint32_t*)&u;
        #pragma unroll
        for (int p = 0; p < 4; p++) {
            float a = rintf(fminf(fmaxf(__fdiv_rn(q[p * 2],     scale), -FP8_MAX_F), FP8_MAX_F));
            float b = rintf(fminf(fmaxf(__fdiv_rn(q[p * 2 + 1], scale), -FP8_MAX_F), FP8_MAX_F));
            __half2 h = __floats2half2_rn(a, b);
            up[p] = *reinterpret_cast<unsigned int*>(&h);
        }
        *reinterpret_cast<uint4*>(&g_xq[(size_t)j * 8]) = u;
    }
}

// ---------------- kernel 4: pipelined HMMA GEMM, warp tile 64x64 ----------------
// out[t, o] = acc(t,o) * (iscale * wscale[o]) + bias[o]
__global__ void __launch_bounds__(256, 1)
gemm_kernel(const float* __restrict__ bias, float* __restrict__ out) {
    extern __shared__ __align__(1024) char smem[];
    const uint32_t smem_base = smem_u32(smem);

    const int tid  = threadIdx.x;
    const int wid  = tid >> 5, lane = tid & 31;
    const int wm   = wid >> 2, wn = wid & 3;      // 2x4 warp grid; warp tile 64x64
    const int g    = lane >> 2, t4 = lane & 3;
    const int bm   = blockIdx.y * BM;
    const int bn   = blockIdx.x * BN;

    const __half* Ag = g_xq + (size_t)bm * K_DIM;
    const __half* Bg = g_wq + (size_t)bn * K_DIM;

    // cp.async: A = 1024 x 16B chunks (4/thread), B = 2048 x 16B chunks (8/thread)
#define LOAD_TILE(kt, s) do {                                                          \
    uint32_t sb = smem_base + (s) * STAGE_BYTES;                                       \
    _Pragma("unroll")                                                                  \
    for (int i = 0; i < 4; i++) {                                                      \
        int idx = tid + i * 256;                                                       \
        int r = idx >> 3, c = idx & 7;                                                 \
        const __half* ga = Ag + (size_t)r * K_DIM + (kt) * BK + c * 8;                 \
        uint32_t sa = sb + sw128((uint32_t)(r * 128 + c * 16));                        \
        asm volatile("cp.async.cg.shared.global [%0], [%1], 16;" :: "r"(sa), "l"(ga)); \
    }                                                                                  \
    _Pragma("unroll")                                                                  \
    for (int i = 0; i < 8; i++) {                                                      \
        int idx = tid + i * 256;                                                       \
        int r = idx >> 3, c = idx & 7;                                                 \
        const __half* gb = Bg + (size_t)r * K_DIM + (kt) * BK + c * 8;                 \
        uint32_t sa = sb + A_STAGE_BYTES + sw128((uint32_t)(r * 128 + c * 16));        \
        asm volatile("cp.async.cg.shared.global [%0], [%1], 16;" :: "r"(sa), "l"(gb)); \
    }                                                                                  \
    asm volatile("cp.async.commit_group;" ::: "memory");                               \
} while (0)

    // ldmatrix per-lane constants
    const int rl = (lane & 7) + ((lane >> 3) & 1) * 8;   // row offset 0..15
    const uint32_t cl = (lane >> 4) * 16;                // +16 bytes for upper 8-lane group

    uint32_t rowA[4], xmA[4], rowB[4], xmB[4];
    #pragma unroll
    for (int im = 0; im < 4; im++) {
        rowA[im] = (uint32_t)(wm * 64 + im * 16 + rl) * 128;
        xmA[im]  = (rowA[im] >> 3) & 0x70;
    }
    #pragma unroll
    for (int in2 = 0; in2 < 4; in2++) {
        rowB[in2] = (uint32_t)(wn * 64 + in2 * 16 + rl) * 128 + A_STAGE_BYTES;
        xmB[in2]  = (rowB[in2] >> 3) & 0x70;
    }

    float acc[4][8][4];
    #pragma unroll
    for (int i = 0; i < 4; i++)
        #pragma unroll
        for (int j = 0; j < 8; j++)
            #pragma unroll
            for (int r = 0; r < 4; r++) acc[i][j][r] = 0.f;

    LOAD_TILE(0, 0);
    LOAD_TILE(1, 1);
    LOAD_TILE(2, 2);

    for (int kt = 0; kt < NT; kt++) {
        const int s = kt % STAGES;
        if (kt < NT - 2) {
            asm volatile("cp.async.wait_group 2;" ::: "memory");
        } else if (kt == NT - 2) {
            asm volatile("cp.async.wait_group 1;" ::: "memory");
        } else {
            asm volatile("cp.async.wait_group 0;" ::: "memory");
        }
        // Single barrier per tile: passing it proves all warps finished tile kt-1,
        // so stage (kt+3)%4 == (kt-1)%4 is reusable.
        __syncthreads();

        if (kt + 3 < NT) LOAD_TILE(kt + 3, (kt + 3) % STAGES);

        const uint32_t stage = smem_base + s * STAGE_BYTES;
        #pragma unroll
        for (int kk8 = 0; kk8 < 4; kk8++) {           // k = kk8*16
            const uint32_t colb = (uint32_t)kk8 * 32 + cl;
            uint32_t a[4][4], bf[4][4];
            #pragma unroll
            for (int im = 0; im < 4; im++) {
                uint32_t ad = stage + rowA[im] + (colb ^ xmA[im]);
                asm volatile("ldmatrix.sync.aligned.m8n8.x4.shared.b16 {%0,%1,%2,%3}, [%4];"
                             : "=r"(a[im][0]), "=r"(a[im][1]), "=r"(a[im][2]), "=r"(a[im][3])
                             : "r"(ad));
            }
            #pragma unroll
            for (int in2 = 0; in2 < 4; in2++) {
                uint32_t ad = stage + rowB[in2] + (colb ^ xmB[in2]);
                asm volatile("ldmatrix.sync.aligned.m8n8.x4.shared.b16 {%0,%1,%2,%3}, [%4];"
                             : "=r"(bf[in2][0]), "=r"(bf[in2][1]), "=r"(bf[in2][2]), "=r"(bf[in2][3])
                             : "r"(ad));
            }
            #pragma unroll
            for (int im = 0; im < 4; im++) {
                #pragma unroll
                for (int in_ = 0; in_ < 8; in_++) {
                    uint32_t b0 = (in_ & 1) ? bf[in_ >> 1][1] : bf[in_ >> 1][0];
                    uint32_t b1 = (in_ & 1) ? bf[in_ >> 1][3] : bf[in_ >> 1][2];
                    float* c = acc[im][in_];
                    asm volatile(
                        "mma.sync.aligned.m16n8k16.row.col.f32.f16.f16.f32 "
                        "{%0,%1,%2,%3}, {%4,%5,%6,%7}, {%8,%9}, {%0,%1,%2,%3};\n"
                        : "+f"(c[0]), "+f"(c[1]), "+f"(c[2]), "+f"(c[3])
                        : "r"(a[im][0]), "r"(a[im][1]), "r"(a[im][2]), "r"(a[im][3]),
                          "r"(b0), "r"(b1));
                }
            }
        }
    }
#undef LOAD_TILE

    // epilogue: dequant + bias
    const float iscale = fmaxf(__fdiv_rn(__uint_as_float(g_amax_bits), FP8_MAX_F), 1e-12f);
    #pragma unroll
    for (int in_ = 0; in_ < 8; in_++) {
        int col = bn + wn * 64 + in_ * 8 + t4 * 2;
        float s0 = iscale * g_wscale[col];
        float s1 = iscale * g_wscale[col + 1];
        float b0 = bias[col];
        float b1 = bias[col + 1];
        #pragma unroll
        for (int im = 0; im < 4; im++) {
            int row = bm + wm * 64 + im * 16 + g;
            float* c = acc[im][in_];
            float2 v0 = make_float2(c[0] * s0 + b0, c[1] * s1 + b1);
            float2 v1 = make_float2(c[2] * s0 + b0, c[3] * s1 + b1);
            *(float2*)&out[(size_t)row * O_DIM + col]       = v0;
            *(float2*)&out[(size_t)(row + 8) * O_DIM + col] = v1;
        }
    }
}

// ---------------- launch ----------------
extern "C" void kernel_launch(void* const* d_in, const int* in_sizes, int n_in,
                              void* d_out, int out_size) {
    const float* x    = (const float*)d_in[0];   // [T, 1024]
    const float* w    = (const float*)d_in[1];   // [1024, 1024]
    const float* bias = (const float*)d_in[2];   // [1024]
    float* out = (float*)d_out;                  // [T, 1024] fp32

    const int n  = in_sizes[0];
    const int n4 = n / 4;
    const int n8 = n / 8;
    const int T  = n / K_DIM;                    // 32768

    reset_kernel<<<1, 1>>>();
    amax_kernel<<<1184, 256>>>(x, n4);
    wq_kernel<<<O_DIM, 128>>>(w);
    xq_kernel<<<2048, 256>>>(x, n8);

    static bool attr_set = false;
    if (!attr_set) {
        cudaFuncSetAttribute(gemm_kernel,
                             cudaFuncAttributeMaxDynamicSharedMemorySize, SMEM_TOTAL);
        attr_set = true;
    }
    dim3 grid(O_DIM / BN, T / BM);               // (4, 256)
    gemm_kernel<<<grid, 256, SMEM_TOTAL>>>(bias, out);
}

// round 11
// speedup vs baseline: 1.0318x; 1.0318x over previous
#include <cuda_runtime.h>
#include <cuda_fp16.h>
#include <cstdint>

#define K_DIM 1024
#define O_DIM 1024
#define FP8_MAX_F 448.0f

// ---- GEMM tiling (HMMA mma.sync path; tcgen05 unavailable at compute_103) ----
#define BM 128
#define BN 128
#define BK 64                  // 128 bytes/row fp16 = one SW128 atom
#define STAGES 3
#define NT (K_DIM / BK)        // 16

#define A_STAGE_BYTES (BM * 128)                        // 16384
#define B_STAGE_BYTES (BN * 128)                        // 16384
#define STAGE_BYTES   (A_STAGE_BYTES + B_STAGE_BYTES)   // 32768
#define SMEM_TOTAL    (STAGES * STAGE_BYTES)            // 98304

static __device__ __forceinline__ uint32_t sw128(uint32_t off) {
    return off ^ ((off >> 3) & 0x70);
}
static __device__ __forceinline__ uint32_t smem_u32(const void* p) {
    uint32_t a;
    asm("{ .reg .u64 t; cvta.to.shared.u64 t, %1; cvt.u32.u64 %0, t; }" : "=r"(a) : "l"(p));
    return a;
}

// ---- scratch (static device globals; no runtime allocation) ----
__device__ unsigned int g_amax_bits;
__device__ float  g_wscale[O_DIM];
__device__ __half g_wq[(size_t)O_DIM * K_DIM];
__device__ __half g_xq[(size_t)32768 * K_DIM];

// ---------------- kernel 0: reset ----------------
__global__ void reset_kernel() { g_amax_bits = 0u; }

// ---------------- kernel 1: global amax of x ----------------
__global__ void amax_kernel(const float* __restrict__ x, int n4) {
    const float4* x4 = (const float4*)x;
    float m = 0.f;
    int stride = gridDim.x * blockDim.x;
    for (int j = blockIdx.x * blockDim.x + threadIdx.x; j < n4; j += stride) {
        float4 v = x4[j];
        m = fmaxf(m, fmaxf(fmaxf(fabsf(v.x), fabsf(v.y)), fmaxf(fabsf(v.z), fabsf(v.w))));
    }
    #pragma unroll
    for (int o = 16; o; o >>= 1) m = fmaxf(m, __shfl_xor_sync(0xffffffffu, m, o));
    __shared__ float sm[8];
    if ((threadIdx.x & 31) == 0) sm[threadIdx.x >> 5] = m;
    __syncthreads();
    if (threadIdx.x < 32) {
        m = (threadIdx.x < (blockDim.x >> 5)) ? sm[threadIdx.x] : 0.f;
        #pragma unroll
        for (int o = 4; o; o >>= 1) m = fmaxf(m, __shfl_xor_sync(0xffffffffu, m, o));
        if (threadIdx.x == 0) atomicMax(&g_amax_bits, __float_as_uint(m));
    }
}

// ---------------- kernel 2: per-row weight amax + quantize to fp16 ----------------
__global__ void wq_kernel(const float* __restrict__ w) {
    int row = blockIdx.x;
    const float* wr = w + (size_t)row * K_DIM;
    float m = 0.f;
    for (int k = threadIdx.x; k < K_DIM; k += 128) m = fmaxf(m, fabsf(wr[k]));
    #pragma unroll
    for (int o = 16; o; o >>= 1) m = fmaxf(m, __shfl_xor_sync(0xffffffffu, m, o));
    __shared__ float sm[4];
    if ((threadIdx.x & 31) == 0) sm[threadIdx.x >> 5] = m;
    __syncthreads();
    float am = fmaxf(fmaxf(sm[0], sm[1]), fmaxf(sm[2], sm[3]));
    float scale = fmaxf(__fdiv_rn(am, FP8_MAX_F), 1e-12f);
    if (threadIdx.x == 0) g_wscale[row] = scale;
    for (int k = threadIdx.x; k < K_DIM; k += 128) {
        float q = rintf(fminf(fmaxf(__fdiv_rn(wr[k], scale), -FP8_MAX_F), FP8_MAX_F));
        g_wq[(size_t)row * K_DIM + k] = __float2half_rn(q);  // exact (integer <= 448)
    }
}

// ---------------- kernel 3: quantize x to fp16 (2x float4 per iter for MLP) ----------------
__global__ void xq_kernel(const float* __restrict__ x, int n8) {
    float scale = fmaxf(__fdiv_rn(__uint_as_float(g_amax_bits), FP8_MAX_F), 1e-12f);
    const float4* x4 = (const float4*)x;
    int stride = gridDim.x * blockDim.x;
    for (int j = blockIdx.x * blockDim.x + threadIdx.x; j < n8; j += stride) {
        float4 v0 = x4[j * 2];
        float4 v1 = x4[j * 2 + 1];
        float q[8];
        q[0] = v0.x; q[1] = v0.y; q[2] = v0.z; q[3] = v0.w;
        q[4] = v1.x; q[5] = v1.y; q[6] = v1.z; q[7] = v1.w;
        uint4 u;
        uint32_t* up = (uint32_t*)&u;
        #pragma unroll
        for (int p = 0; p < 4; p++) {
            float a = rintf(fminf(fmaxf(__fdiv_rn(q[p * 2],     scale), -FP8_MAX_F), FP8_MAX_F));
            float b = rintf(fminf(fmaxf(__fdiv_rn(q[p * 2 + 1], scale), -FP8_MAX_F), FP8_MAX_F));
            __half2 h = __floats2half2_rn(a, b);
            up[p] = *reinterpret_cast<unsigned int*>(&h);
        }
        *reinterpret_cast<uint4*>(&g_xq[(size_t)j * 8]) = u;
    }
}

// ---------------- kernel 4: pipelined HMMA GEMM (frag double-buffer) ----------------
// out[t, o] = acc(t,o) * (iscale * wscale[o]) + bias[o]
__global__ void __launch_bounds__(256, 2)
gemm_kernel(const float* __restrict__ bias, float* __restrict__ out) {
    extern __shared__ __align__(1024) char smem[];
    const uint32_t smem_base = smem_u32(smem);

    const int tid  = threadIdx.x;
    const int wid  = tid >> 5, lane = tid & 31;
    const int wm   = wid >> 2, wn = wid & 3;      // 2x4 warp grid; warp tile 64x32
    const int g    = lane >> 2, t4 = lane & 3;
    const int bm   = blockIdx.y * BM;
    const int bn   = blockIdx.x * BN;

    const __half* Ag = g_xq + (size_t)bm * K_DIM;
    const __half* Bg = g_wq + (size_t)bn * K_DIM;

#define LOAD_TILE(kt, s) do {                                                          \
    uint32_t sb = smem_base + (s) * STAGE_BYTES;                                       \
    _Pragma("unroll")                                                                  \
    for (int i = 0; i < 4; i++) {                                                      \
        int idx = tid + i * 256;                                                       \
        int r = idx >> 3, c = idx & 7;                                                 \
        const __half* ga = Ag + (size_t)r * K_DIM + (kt) * BK + c * 8;                 \
        uint32_t sa = sb + sw128((uint32_t)(r * 128 + c * 16));                        \
        asm volatile("cp.async.cg.shared.global [%0], [%1], 16;" :: "r"(sa), "l"(ga)); \
    }                                                                                  \
    _Pragma("unroll")                                                                  \
    for (int i = 0; i < 4; i++) {                                                      \
        int idx = tid + i * 256;                                                       \
        int r = idx >> 3, c = idx & 7;                                                 \
        const __half* gb = Bg + (size_t)r * K_DIM + (kt) * BK + c * 8;                 \
        uint32_t sa = sb + A_STAGE_BYTES + sw128((uint32_t)(r * 128 + c * 16));        \
        asm volatile("cp.async.cg.shared.global [%0], [%1], 16;" :: "r"(sa), "l"(gb)); \
    }                                                                                  \
    asm volatile("cp.async.commit_group;" ::: "memory");                               \
} while (0)

    // ldmatrix per-lane constants
    const int rl = (lane & 7) + ((lane >> 3) & 1) * 8;   // row offset 0..15
    const uint32_t cl = (lane >> 4) * 16;                // +16 bytes for upper 8-lane group

    uint32_t rowA[4], xmA[4], rowB[2], xmB[2];
    #pragma unroll
    for (int im = 0; im < 4; im++) {
        rowA[im] = (uint32_t)(wm * 64 + im * 16 + rl) * 128;
        xmA[im]  = (rowA[im] >> 3) & 0x70;
    }
    #pragma unroll
    for (int in2 = 0; in2 < 2; in2++) {
        rowB[in2] = (uint32_t)(wn * 32 + in2 * 16 + rl) * 128 + A_STAGE_BYTES;
        xmB[in2]  = (rowB[in2] >> 3) & 0x70;
    }

    // fragment load for one K16 step into buffer (A[4][4], B[2][4])
#define LDFRAG(stage, kk8, Abuf, Bbuf) do {                                            \
    const uint32_t colb = (uint32_t)(kk8) * 32 + cl;                                   \
    _Pragma("unroll")                                                                  \
    for (int im = 0; im < 4; im++) {                                                   \
        uint32_t ad = (stage) + rowA[im] + (colb ^ xmA[im]);                           \
        asm volatile("ldmatrix.sync.aligned.m8n8.x4.shared.b16 {%0,%1,%2,%3}, [%4];"   \
                     : "=r"((Abuf)[im][0]), "=r"((Abuf)[im][1]),                       \
                       "=r"((Abuf)[im][2]), "=r"((Abuf)[im][3])                        \
                     : "r"(ad));                                                       \
    }                                                                                  \
    _Pragma("unroll")                                                                  \
    for (int in2 = 0; in2 < 2; in2++) {                                                \
        uint32_t ad = (stage) + rowB[in2] + (colb ^ xmB[in2]);                         \
        asm volatile("ldmatrix.sync.aligned.m8n8.x4.shared.b16 {%0,%1,%2,%3}, [%4];"   \
                     : "=r"((Bbuf)[in2][0]), "=r"((Bbuf)[in2][1]),                     \
                       "=r"((Bbuf)[in2][2]), "=r"((Bbuf)[in2][3])                      \
                     : "r"(ad));                                                       \
    }                                                                                  \
} while (0)

    float acc[4][4][4];
    #pragma unroll
    for (int i = 0; i < 4; i++)
        #pragma unroll
        for (int j = 0; j < 4; j++)
            #pragma unroll
            for (int r = 0; r < 4; r++) acc[i][j][r] = 0.f;

    LOAD_TILE(0, 0);
    LOAD_TILE(1, 1);

    uint32_t afr[2][4][4], bfr[2][2][4];

    for (int kt = 0; kt < NT; kt++) {
        const int s = kt % STAGES;
        if (kt == NT - 1) {
            asm volatile("cp.async.wait_group 0;" ::: "memory");
        } else {
            asm volatile("cp.async.wait_group 1;" ::: "memory");
        }
        // Single barrier per tile: passing it proves all warps finished tile kt-1,
        // so stage (kt+2)%3 == (kt-1)%3 is reusable.
        __syncthreads();

        if (kt + 2 < NT) LOAD_TILE(kt + 2, (kt + 2) % STAGES);

        const uint32_t stage = smem_base + s * STAGE_BYTES;

        LDFRAG(stage, 0, afr[0], bfr[0]);
        #pragma unroll
        for (int kk8 = 0; kk8 < 4; kk8++) {
            const int cur = kk8 & 1, nxt = cur ^ 1;
            if (kk8 < 3) LDFRAG(stage, kk8 + 1, afr[nxt], bfr[nxt]);
            #pragma unroll
            for (int im = 0; im < 4; im++) {
                #pragma unroll
                for (int in_ = 0; in_ < 4; in_++) {
                    uint32_t b0 = (in_ & 1) ? bfr[cur][in_ >> 1][1] : bfr[cur][in_ >> 1][0];
                    uint32_t b1 = (in_ & 1) ? bfr[cur][in_ >> 1][3] : bfr[cur][in_ >> 1][2];
                    float* c = acc[im][in_];
                    asm volatile(
                        "mma.sync.aligned.m16n8k16.row.col.f32.f16.f16.f32 "
                        "{%0,%1,%2,%3}, {%4,%5,%6,%7}, {%8,%9}, {%0,%1,%2,%3};\n"
                        : "+f"(c[0]), "+f"(c[1]), "+f"(c[2]), "+f"(c[3])
                        : "r"(afr[cur][im][0]), "r"(afr[cur][im][1]),
                          "r"(afr[cur][im][2]), "r"(afr[cur][im][3]),
                          "r"(b0), "r"(b1));
                }
            }
        }
    }
#undef LOAD_TILE
#undef LDFRAG

    // epilogue: dequant + bias
    const float iscale = fmaxf(__fdiv_rn(__uint_as_float(g_amax_bits), FP8_MAX_F), 1e-12f);
    #pragma unroll
    for (int in_ = 0; in_ < 4; in_++) {
        int col = bn + wn * 32 + in_ * 8 + t4 * 2;
        float s0 = iscale * g_wscale[col];
        float s1 = iscale * g_wscale[col + 1];
        float b0 = bias[col];
        float b1 = bias[col + 1];
        #pragma unroll
        for (int im = 0; im < 4; im++) {
            int row = bm + wm * 64 + im * 16 + g;
            float* c = acc[im][in_];
            float2 v0 = make_float2(c[0] * s0 + b0, c[1] * s1 + b1);
            float2 v1 = make_float2(c[2] * s0 + b0, c[3] * s1 + b1);
            *(float2*)&out[(size_t)row * O_DIM + col]       = v0;
            *(float2*)&out[(size_t)(row + 8) * O_DIM + col] = v1;
        }
    }
}

// ---------------- launch ----------------
extern "C" void kernel_launch(void* const* d_in, const int* in_sizes, int n_in,
                              void* d_out, int out_size) {
    const float* x    = (const float*)d_in[0];   // [T, 1024]
    const float* w    = (const float*)d_in[1];   // [1024, 1024]
    const float* bias = (const float*)d_in[2];   // [1024]
    float* out = (float*)d_out;                  // [T, 1024] fp32

    const int n  = in_sizes[0];
    const int n4 = n / 4;
    const int n8 = n / 8;
    const int T  = n / K_DIM;                    // 32768

    reset_kernel<<<1, 1>>>();
    amax_kernel<<<1184, 256>>>(x, n4);
    wq_kernel<<<O_DIM, 128>>>(w);
    xq_kernel<<<2048, 256>>>(x, n8);

    cudaFuncSetAttribute(gemm_kernel,
                         cudaFuncAttributeMaxDynamicSharedMemorySize, SMEM_TOTAL);
    dim3 grid(O_DIM / BN, T / BM);               // (8, 256)
    gemm_kernel<<<grid, 256, SMEM_TOTAL>>>(bias, out);
}

// round 12
// speedup vs baseline: 1.0819x; 1.0485x over previous
#include <cuda_runtime.h>
#include <cuda_fp16.h>
#include <cstdint>

#define K_DIM 1024
#define O_DIM 1024
#define FP8_MAX_F 448.0f
#define AMAX_BLOCKS 1184

// ---- GEMM tiling (HMMA mma.sync path; tcgen05 unavailable at compute_103) ----
#define BM 128
#define BN 128
#define BK 64                  // 128 bytes/row fp16 = one SW128 atom
#define STAGES 3
#define NT (K_DIM / BK)        // 16

#define A_STAGE_BYTES (BM * 128)                        // 16384
#define B_STAGE_BYTES (BN * 128)                        // 16384
#define STAGE_BYTES   (A_STAGE_BYTES + B_STAGE_BYTES)   // 32768
#define SMEM_TOTAL    (STAGES * STAGE_BYTES)            // 98304

static __device__ __forceinline__ uint32_t sw128(uint32_t off) {
    return off ^ ((off >> 3) & 0x70);
}
static __device__ __forceinline__ uint32_t smem_u32(const void* p) {
    uint32_t a;
    asm("{ .reg .u64 t; cvta.to.shared.u64 t, %1; cvt.u32.u64 %0, t; }" : "=r"(a) : "l"(p));
    return a;
}

// ---- scratch (static device globals; no runtime allocation) ----
__device__ float  g_partial[AMAX_BLOCKS];   // per-block amax partials (overwritten each launch)
__device__ float  g_scale;                  // final input scale (same value stored by all xq blocks)
__device__ float  g_wscale[O_DIM];
__device__ __half g_wq[(size_t)O_DIM * K_DIM];
__device__ __half g_xq[(size_t)32768 * K_DIM];

// ---------------- kernel 1: fused weight-quant + x-amax partials ----------------
// blocks 0..1023: per-row weight amax + quantize; blocks 1024..2207: x amax partial
__global__ void prep_kernel(const float* __restrict__ x, const float* __restrict__ w, int n4) {
    const int tid = threadIdx.x;
    if (blockIdx.x < O_DIM) {
        // ---- weight row quantization ----
        const int row = blockIdx.x;
        const float* wr = w + (size_t)row * K_DIM;
        float m = 0.f;
        for (int k = tid; k < K_DIM; k += 256) m = fmaxf(m, fabsf(wr[k]));
        #pragma unroll
        for (int o = 16; o; o >>= 1) m = fmaxf(m, __shfl_xor_sync(0xffffffffu, m, o));
        __shared__ float sm[8];
        if ((tid & 31) == 0) sm[tid >> 5] = m;
        __syncthreads();
        float am = sm[0];
        #pragma unroll
        for (int i = 1; i < 8; i++) am = fmaxf(am, sm[i]);
        float scale = fmaxf(__fdiv_rn(am, FP8_MAX_F), 1e-12f);
        if (tid == 0) g_wscale[row] = scale;
        for (int k = tid; k < K_DIM; k += 256) {
            float q = rintf(fminf(fmaxf(__fdiv_rn(wr[k], scale), -FP8_MAX_F), FP8_MAX_F));
            g_wq[(size_t)row * K_DIM + k] = __float2half_rn(q);  // exact (integer <= 448)
        }
    } else {
        // ---- x amax partial (plain store, no init / no atomics needed) ----
        const int b = blockIdx.x - O_DIM;
        const float4* x4 = (const float4*)x;
        float m = 0.f;
        const int stride = AMAX_BLOCKS * 256;
        for (int j = b * 256 + tid; j < n4; j += stride) {
            float4 v = x4[j];
            m = fmaxf(m, fmaxf(fmaxf(fabsf(v.x), fabsf(v.y)), fmaxf(fabsf(v.z), fabsf(v.w))));
        }
        #pragma unroll
        for (int o = 16; o; o >>= 1) m = fmaxf(m, __shfl_xor_sync(0xffffffffu, m, o));
        __shared__ float sm2[8];
        if ((tid & 31) == 0) sm2[tid >> 5] = m;
        __syncthreads();
        if (tid == 0) {
            float am = sm2[0];
            #pragma unroll
            for (int i = 1; i < 8; i++) am = fmaxf(am, sm2[i]);
            g_partial[b] = am;
        }
    }
}

// ---------------- kernel 2: quantize x to fp16 (partials reduce + recip-mul) ----------------
__global__ void xq_kernel(const float* __restrict__ x, int n8) {
    const int tid = threadIdx.x;
    // reduce the 1184 partial maxima (identical result in every block)
    float m = 0.f;
    for (int i = tid; i < AMAX_BLOCKS; i += 256) m = fmaxf(m, g_partial[i]);
    #pragma unroll
    for (int o = 16; o; o >>= 1) m = fmaxf(m, __shfl_xor_sync(0xffffffffu, m, o));
    __shared__ float sm[8];
    __shared__ float s_inv;
    if ((tid & 31) == 0) sm[tid >> 5] = m;
    __syncthreads();
    if (tid == 0) {
        float am = sm[0];
        #pragma unroll
        for (int i = 1; i < 8; i++) am = fmaxf(am, sm[i]);
        float scale = fmaxf(__fdiv_rn(am, FP8_MAX_F), 1e-12f);
        g_scale = scale;                 // same value from every block: benign
        s_inv = __fdiv_rn(1.0f, scale);
    }
    __syncthreads();
    const float inv = s_inv;

    const float4* x4 = (const float4*)x;
    int stride = gridDim.x * blockDim.x;
    for (int j = blockIdx.x * blockDim.x + tid; j < n8; j += stride) {
        float4 v0 = x4[j * 2];
        float4 v1 = x4[j * 2 + 1];
        float q[8];
        q[0] = v0.x; q[1] = v0.y; q[2] = v0.z; q[3] = v0.w;
        q[4] = v1.x; q[5] = v1.y; q[6] = v1.z; q[7] = v1.w;
        uint4 u;
        uint32_t* up = (uint32_t*)&u;
        #pragma unroll
        for (int p = 0; p < 4; p++) {
            float a = rintf(fminf(fmaxf(q[p * 2]     * inv, -FP8_MAX_F), FP8_MAX_F));
            float b = rintf(fminf(fmaxf(q[p * 2 + 1] * inv, -FP8_MAX_F), FP8_MAX_F));
            __half2 h = __floats2half2_rn(a, b);
            up[p] = *reinterpret_cast<unsigned int*>(&h);
        }
        *reinterpret_cast<uint4*>(&g_xq[(size_t)j * 8]) = u;
    }
}

// ---------------- kernel 3: pipelined HMMA GEMM (cp.async + ldmatrix) ----------------
// out[t, o] = acc(t,o) * (g_scale * wscale[o]) + bias[o]
__global__ void __launch_bounds__(256, 2)
gemm_kernel(const float* __restrict__ bias, float* __restrict__ out) {
    extern __shared__ __align__(1024) char smem[];
    const uint32_t smem_base = smem_u32(smem);

    const int tid  = threadIdx.x;
    const int wid  = tid >> 5, lane = tid & 31;
    const int wm   = wid >> 2, wn = wid & 3;      // 2x4 warp grid; warp tile 64x32
    const int g    = lane >> 2, t4 = lane & 3;
    const int bm   = blockIdx.y * BM;
    const int bn   = blockIdx.x * BN;

    const __half* Ag = g_xq + (size_t)bm * K_DIM;
    const __half* Bg = g_wq + (size_t)bn * K_DIM;

#define LOAD_TILE(kt, s) do {                                                          \
    uint32_t sb = smem_base + (s) * STAGE_BYTES;                                       \
    _Pragma("unroll")                                                                  \
    for (int i = 0; i < 4; i++) {                                                      \
        int idx = tid + i * 256;                                                       \
        int r = idx >> 3, c = idx & 7;                                                 \
        const __half* ga = Ag + (size_t)r * K_DIM + (kt) * BK + c * 8;                 \
        uint32_t sa = sb + sw128((uint32_t)(r * 128 + c * 16));                        \
        asm volatile("cp.async.cg.shared.global [%0], [%1], 16;" :: "r"(sa), "l"(ga)); \
    }                                                                                  \
    _Pragma("unroll")                                                                  \
    for (int i = 0; i < 4; i++) {                                                      \
        int idx = tid + i * 256;                                                       \
        int r = idx >> 3, c = idx & 7;                                                 \
        const __half* gb = Bg + (size_t)r * K_DIM + (kt) * BK + c * 8;                 \
        uint32_t sa = sb + A_STAGE_BYTES + sw128((uint32_t)(r * 128 + c * 16));        \
        asm volatile("cp.async.cg.shared.global [%0], [%1], 16;" :: "r"(sa), "l"(gb)); \
    }                                                                                  \
    asm volatile("cp.async.commit_group;" ::: "memory");                               \
} while (0)

    // ldmatrix per-lane constants
    const int rl = (lane & 7) + ((lane >> 3) & 1) * 8;   // row offset 0..15
    const uint32_t cl = (lane >> 4) * 16;                // +16 bytes for upper 8-lane group

    uint32_t rowA[4], xmA[4], rowB[2], xmB[2];
    #pragma unroll
    for (int im = 0; im < 4; im++) {
        rowA[im] = (uint32_t)(wm * 64 + im * 16 + rl) * 128;
        xmA[im]  = (rowA[im] >> 3) & 0x70;
    }
    #pragma unroll
    for (int in2 = 0; in2 < 2; in2++) {
        rowB[in2] = (uint32_t)(wn * 32 + in2 * 16 + rl) * 128 + A_STAGE_BYTES;
        xmB[in2]  = (rowB[in2] >> 3) & 0x70;
    }

    float acc[4][4][4];
    #pragma unroll
    for (int i = 0; i < 4; i++)
        #pragma unroll
        for (int j = 0; j < 4; j++)
            #pragma unroll
            for (int r = 0; r < 4; r++) acc[i][j][r] = 0.f;

    LOAD_TILE(0, 0);
    LOAD_TILE(1, 1);

    for (int kt = 0; kt < NT; kt++) {
        const int s = kt % STAGES;
        if (kt == NT - 1) {
            asm volatile("cp.async.wait_group 0;" ::: "memory");
        } else {
            asm volatile("cp.async.wait_group 1;" ::: "memory");
        }
        // Single barrier per tile: passing it proves all warps finished tile kt-1,
        // so stage (kt+2)%3 == (kt-1)%3 is reusable.
        __syncthreads();

        if (kt + 2 < NT) LOAD_TILE(kt + 2, (kt + 2) % STAGES);

        const uint32_t stage = smem_base + s * STAGE_BYTES;
        #pragma unroll
        for (int kk8 = 0; kk8 < 4; kk8++) {           // k = kk8*16
            const uint32_t colb = (uint32_t)kk8 * 32 + cl;
            uint32_t a[4][4], bf[2][4];
            #pragma unroll
            for (int im = 0; im < 4; im++) {
                uint32_t ad = stage + rowA[im] + (colb ^ xmA[im]);
                asm volatile("ldmatrix.sync.aligned.m8n8.x4.shared.b16 {%0,%1,%2,%3}, [%4];"
                             : "=r"(a[im][0]), "=r"(a[im][1]), "=r"(a[im][2]), "=r"(a[im][3])
                             : "r"(ad));
            }
            #pragma unroll
            for (int in2 = 0; in2 < 2; in2++) {
                uint32_t ad = stage + rowB[in2] + (colb ^ xmB[in2]);
                asm volatile("ldmatrix.sync.aligned.m8n8.x4.shared.b16 {%0,%1,%2,%3}, [%4];"
                             : "=r"(bf[in2][0]), "=r"(bf[in2][1]), "=r"(bf[in2][2]), "=r"(bf[in2][3])
                             : "r"(ad));
            }
            #pragma unroll
            for (int im = 0; im < 4; im++) {
                #pragma unroll
                for (int in_ = 0; in_ < 4; in_++) {
                    uint32_t b0 = (in_ & 1) ? bf[in_ >> 1][1] : bf[in_ >> 1][0];
                    uint32_t b1 = (in_ & 1) ? bf[in_ >> 1][3] : bf[in_ >> 1][2];
                    float* c = acc[im][in_];
                    asm volatile(
                        "mma.sync.aligned.m16n8k16.row.col.f32.f16.f16.f32 "
                        "{%0,%1,%2,%3}, {%4,%5,%6,%7}, {%8,%9}, {%0,%1,%2,%3};\n"
                        : "+f"(c[0]), "+f"(c[1]), "+f"(c[2]), "+f"(c[3])
                        : "r"(a[im][0]), "r"(a[im][1]), "r"(a[im][2]), "r"(a[im][3]),
                          "r"(b0), "r"(b1));
                }
            }
        }
    }
#undef LOAD_TILE

    // epilogue: dequant + bias
    const float iscale = g_scale;
    #pragma unroll
    for (int in_ = 0; in_ < 4; in_++) {
        int col = bn + wn * 32 + in_ * 8 + t4 * 2;
        float s0 = iscale * g_wscale[col];
        float s1 = iscale * g_wscale[col + 1];
        float b0 = bias[col];
        float b1 = bias[col + 1];
        #pragma unroll
        for (int im = 0; im < 4; im++) {
            int row = bm + wm * 64 + im * 16 + g;
            float* c = acc[im][in_];
            float2 v0 = make_float2(c[0] * s0 + b0, c[1] * s1 + b1);
            float2 v1 = make_float2(c[2] * s0 + b0, c[3] * s1 + b1);
            *(float2*)&out[(size_t)row * O_DIM + col]       = v0;
            *(float2*)&out[(size_t)(row + 8) * O_DIM + col] = v1;
        }
    }
}

// ---------------- launch ----------------
extern "C" void kernel_launch(void* const* d_in, const int* in_sizes, int n_in,
                              void* d_out, int out_size) {
    const float* x    = (const float*)d_in[0];   // [T, 1024]
    const float* w    = (const float*)d_in[1];   // [1024, 1024]
    const float* bias = (const float*)d_in[2];   // [1024]
    float* out = (float*)d_out;                  // [T, 1024] fp32

    const int n  = in_sizes[0];
    const int n4 = n / 4;
    const int n8 = n / 8;
    const int T  = n / K_DIM;                    // 32768

    prep_kernel<<<O_DIM + AMAX_BLOCKS, 256>>>(x, w, n4);
    xq_kernel<<<2048, 256>>>(x, n8);

    cudaFuncSetAttribute(gemm_kernel,
                         cudaFuncAttributeMaxDynamicSharedMemorySize, SMEM_TOTAL);
    dim3 grid(O_DIM / BN, T / BM);               // (8, 256)
    gemm_kernel<<<grid, 256, SMEM_TOTAL>>>(bias, out);
}

// round 13
// speedup vs baseline: 1.0927x; 1.0100x over previous
#include <cuda_runtime.h>
#include <cuda_fp16.h>
#include <cstdint>

#define K_DIM 1024
#define O_DIM 1024
#define FP8_MAX_F 448.0f
#define AMAX_BLOCKS 1184

// ---- GEMM tiling (HMMA mma.sync path; tcgen05 unavailable at compute_103) ----
#define BM 128
#define BN 128
#define BK 64                  // 128 bytes/row fp16 = one SW128 atom
#define STAGES 3
#define NT (K_DIM / BK)        // 16

#define A_STAGE_BYTES (BM * 128)                        // 16384
#define B_STAGE_BYTES (BN * 128)                        // 16384
#define STAGE_BYTES   (A_STAGE_BYTES + B_STAGE_BYTES)   // 32768
#define SMEM_TOTAL    (STAGES * STAGE_BYTES)            // 98304

static __device__ __forceinline__ uint32_t sw128(uint32_t off) {
    return off ^ ((off >> 3) & 0x70);
}
static __device__ __forceinline__ uint32_t smem_u32(const void* p) {
    uint32_t a;
    asm("{ .reg .u64 t; cvta.to.shared.u64 t, %1; cvt.u32.u64 %0, t; }" : "=r"(a) : "l"(p));
    return a;
}

// ---- scratch (static device globals; no runtime allocation) ----
__device__ float  g_partial[AMAX_BLOCKS];   // per-block amax partials (overwritten each launch)
__device__ float  g_scale;                  // final input scale (same value stored by all xq blocks)
__device__ float  g_wscale[O_DIM];
__device__ __half g_wq[(size_t)O_DIM * K_DIM];
__device__ __half g_xq[(size_t)32768 * K_DIM];

// ---------------- kernel 1: fused weight-quant + x-amax partials ----------------
// blocks 0..1023: per-row weight amax + quantize; blocks 1024..2207: x amax partial
__global__ void prep_kernel(const float* __restrict__ x, const float* __restrict__ w, int n4) {
    const int tid = threadIdx.x;
    if (blockIdx.x < O_DIM) {
        // ---- weight row quantization ----
        const int row = blockIdx.x;
        const float* wr = w + (size_t)row * K_DIM;
        float m = 0.f;
        for (int k = tid; k < K_DIM; k += 256) m = fmaxf(m, fabsf(wr[k]));
        #pragma unroll
        for (int o = 16; o; o >>= 1) m = fmaxf(m, __shfl_xor_sync(0xffffffffu, m, o));
        __shared__ float sm[8];
        if ((tid & 31) == 0) sm[tid >> 5] = m;
        __syncthreads();
        float am = sm[0];
        #pragma unroll
        for (int i = 1; i < 8; i++) am = fmaxf(am, sm[i]);
        float scale = fmaxf(__fdiv_rn(am, FP8_MAX_F), 1e-12f);
        if (tid == 0) g_wscale[row] = scale;
        for (int k = tid; k < K_DIM; k += 256) {
            float q = rintf(fminf(fmaxf(__fdiv_rn(wr[k], scale), -FP8_MAX_F), FP8_MAX_F));
            g_wq[(size_t)row * K_DIM + k] = __float2half_rn(q);  // exact (integer <= 448)
        }
    } else {
        // ---- x amax partial: 2x float4 per iter (MLP), plain store (no init/atomics) ----
        const int b = blockIdx.x - O_DIM;
        const float4* x4 = (const float4*)x;
        float m0 = 0.f, m1 = 0.f;
        const int half4 = n4 >> 1;                 // n4 = 8388608, even
        const int stride = AMAX_BLOCKS * 256;
        for (int j = b * 256 + tid; j < half4; j += stride) {
            float4 v0 = x4[j];
            float4 v1 = x4[j + half4];
            m0 = fmaxf(m0, fmaxf(fmaxf(fabsf(v0.x), fabsf(v0.y)), fmaxf(fabsf(v0.z), fabsf(v0.w))));
            m1 = fmaxf(m1, fmaxf(fmaxf(fabsf(v1.x), fabsf(v1.y)), fmaxf(fabsf(v1.z), fabsf(v1.w))));
        }
        float m = fmaxf(m0, m1);
        #pragma unroll
        for (int o = 16; o; o >>= 1) m = fmaxf(m, __shfl_xor_sync(0xffffffffu, m, o));
        __shared__ float sm2[8];
        if ((tid & 31) == 0) sm2[tid >> 5] = m;
        __syncthreads();
        if (tid == 0) {
            float am = sm2[0];
            #pragma unroll
            for (int i = 1; i < 8; i++) am = fmaxf(am, sm2[i]);
            g_partial[b] = am;
        }
    }
}

// ---------------- kernel 2: quantize x to fp16 (partials reduce + recip-mul) ----------------
__global__ void xq_kernel(const float* __restrict__ x, int n8) {
    const int tid = threadIdx.x;
    // reduce the 1184 partial maxima (identical result in every block)
    float m = 0.f;
    #pragma unroll 5
    for (int i = tid; i < AMAX_BLOCKS; i += 256) m = fmaxf(m, g_partial[i]);
    #pragma unroll
    for (int o = 16; o; o >>= 1) m = fmaxf(m, __shfl_xor_sync(0xffffffffu, m, o));
    __shared__ float sm[8];
    __shared__ float s_inv;
    if ((tid & 31) == 0) sm[tid >> 5] = m;
    __syncthreads();
    if (tid == 0) {
        float am = sm[0];
        #pragma unroll
        for (int i = 1; i < 8; i++) am = fmaxf(am, sm[i]);
        float scale = fmaxf(__fdiv_rn(am, FP8_MAX_F), 1e-12f);
        g_scale = scale;                 // same value from every block: benign
        s_inv = __fdiv_rn(1.0f, scale);
    }
    __syncthreads();
    const float inv = s_inv;

    const float4* x4 = (const float4*)x;
    int stride = gridDim.x * blockDim.x;
    for (int j = blockIdx.x * blockDim.x + tid; j < n8; j += stride) {
        float4 v0 = __ldcs(&x4[j * 2]);      // last use of x: stream, don't pollute L2
        float4 v1 = __ldcs(&x4[j * 2 + 1]);
        float q[8];
        q[0] = v0.x; q[1] = v0.y; q[2] = v0.z; q[3] = v0.w;
        q[4] = v1.x; q[5] = v1.y; q[6] = v1.z; q[7] = v1.w;
        uint4 u;
        uint32_t* up = (uint32_t*)&u;
        #pragma unroll
        for (int p = 0; p < 4; p++) {
            float a = rintf(fminf(fmaxf(q[p * 2]     * inv, -FP8_MAX_F), FP8_MAX_F));
            float b = rintf(fminf(fmaxf(q[p * 2 + 1] * inv, -FP8_MAX_F), FP8_MAX_F));
            __half2 h = __floats2half2_rn(a, b);
            up[p] = *reinterpret_cast<unsigned int*>(&h);
        }
        *reinterpret_cast<uint4*>(&g_xq[(size_t)j * 8]) = u;   // keep cacheable: GEMM re-reads
    }
}

// ---------------- kernel 3: pipelined HMMA GEMM (cp.async + ldmatrix) ----------------
// out[t, o] = acc(t,o) * (g_scale * wscale[o]) + bias[o]
__global__ void __launch_bounds__(256, 2)
gemm_kernel(const float* __restrict__ bias, float* __restrict__ out) {
    extern __shared__ __align__(1024) char smem[];
    const uint32_t smem_base = smem_u32(smem);

    const int tid  = threadIdx.x;
    const int wid  = tid >> 5, lane = tid & 31;
    const int wm   = wid >> 2, wn = wid & 3;      // 2x4 warp grid; warp tile 64x32
    const int g    = lane >> 2, t4 = lane & 3;
    const int bm   = blockIdx.y * BM;
    const int bn   = blockIdx.x * BN;

    const __half* Ag = g_xq + (size_t)bm * K_DIM;
    const __half* Bg = g_wq + (size_t)bn * K_DIM;

#define LOAD_TILE(kt, s) do {                                                          \
    uint32_t sb = smem_base + (s) * STAGE_BYTES;                                       \
    _Pragma("unroll")                                                                  \
    for (int i = 0; i < 4; i++) {                                                      \
        int idx = tid + i * 256;                                                       \
        int r = idx >> 3, c = idx & 7;                                                 \
        const __half* ga = Ag + (size_t)r * K_DIM + (kt) * BK + c * 8;                 \
        uint32_t sa = sb + sw128((uint32_t)(r * 128 + c * 16));                        \
        asm volatile("cp.async.cg.shared.global [%0], [%1], 16;" :: "r"(sa), "l"(ga)); \
    }                                                                                  \
    _Pragma("unroll")                                                                  \
    for (int i = 0; i < 4; i++) {                                                      \
        int idx = tid + i * 256;                                                       \
        int r = idx >> 3, c = idx & 7;                                                 \
        const __half* gb = Bg + (size_t)r * K_DIM + (kt) * BK + c * 8;                 \
        uint32_t sa = sb + A_STAGE_BYTES + sw128((uint32_t)(r * 128 + c * 16));        \
        asm volatile("cp.async.cg.shared.global [%0], [%1], 16;" :: "r"(sa), "l"(gb)); \
    }                                                                                  \
    asm volatile("cp.async.commit_group;" ::: "memory");                               \
} while (0)

    // ldmatrix per-lane constants
    const int rl = (lane & 7) + ((lane >> 3) & 1) * 8;   // row offset 0..15
    const uint32_t cl = (lane >> 4) * 16;                // +16 bytes for upper 8-lane group

    uint32_t rowA[4], xmA[4], rowB[2], xmB[2];
    #pragma unroll
    for (int im = 0; im < 4; im++) {
        rowA[im] = (uint32_t)(wm * 64 + im * 16 + rl) * 128;
        xmA[im]  = (rowA[im] >> 3) & 0x70;
    }
    #pragma unroll
    for (int in2 = 0; in2 < 2; in2++) {
        rowB[in2] = (uint32_t)(wn * 32 + in2 * 16 + rl) * 128 + A_STAGE_BYTES;
        xmB[in2]  = (rowB[in2] >> 3) & 0x70;
    }

    float acc[4][4][4];
    #pragma unroll
    for (int i = 0; i < 4; i++)
        #pragma unroll
        for (int j = 0; j < 4; j++)
            #pragma unroll
            for (int r = 0; r < 4; r++) acc[i][j][r] = 0.f;

    LOAD_TILE(0, 0);
    LOAD_TILE(1, 1);

    for (int kt = 0; kt < NT; kt++) {
        const int s = kt % STAGES;
        if (kt == NT - 1) {
            asm volatile("cp.async.wait_group 0;" ::: "memory");
        } else {
            asm volatile("cp.async.wait_group 1;" ::: "memory");
        }
        // Single barrier per tile: passing it proves all warps finished tile kt-1,
        // so stage (kt+2)%3 == (kt-1)%3 is reusable.
        __syncthreads();

        if (kt + 2 < NT) LOAD_TILE(kt + 2, (kt + 2) % STAGES);

        const uint32_t stage = smem_base + s * STAGE_BYTES;
        #pragma unroll
        for (int kk8 = 0; kk8 < 4; kk8++) {           // k = kk8*16
            const uint32_t colb = (uint32_t)kk8 * 32 + cl;
            uint32_t a[4][4], bf[2][4];
            #pragma unroll
            for (int im = 0; im < 4; im++) {
                uint32_t ad = stage + rowA[im] + (colb ^ xmA[im]);
                asm volatile("ldmatrix.sync.aligned.m8n8.x4.shared.b16 {%0,%1,%2,%3}, [%4];"
                             : "=r"(a[im][0]), "=r"(a[im][1]), "=r"(a[im][2]), "=r"(a[im][3])
                             : "r"(ad));
            }
            #pragma unroll
            for (int in2 = 0; in2 < 2; in2++) {
                uint32_t ad = stage + rowB[in2] + (colb ^ xmB[in2]);
                asm volatile("ldmatrix.sync.aligned.m8n8.x4.shared.b16 {%0,%1,%2,%3}, [%4];"
                             : "=r"(bf[in2][0]), "=r"(bf[in2][1]), "=r"(bf[in2][2]), "=r"(bf[in2][3])
                             : "r"(ad));
            }
            #pragma unroll
            for (int im = 0; im < 4; im++) {
                #pragma unroll
                for (int in_ = 0; in_ < 4; in_++) {
                    uint32_t b0 = (in_ & 1) ? bf[in_ >> 1][1] : bf[in_ >> 1][0];
                    uint32_t b1 = (in_ & 1) ? bf[in_ >> 1][3] : bf[in_ >> 1][2];
                    float* c = acc[im][in_];
                    asm volatile(
                        "mma.sync.aligned.m16n8k16.row.col.f32.f16.f16.f32 "
                        "{%0,%1,%2,%3}, {%4,%5,%6,%7}, {%8,%9}, {%0,%1,%2,%3};\n"
                        : "+f"(c[0]), "+f"(c[1]), "+f"(c[2]), "+f"(c[3])
                        : "r"(a[im][0]), "r"(a[im][1]), "r"(a[im][2]), "r"(a[im][3]),
                          "r"(b0), "r"(b1));
                }
            }
        }
    }
#undef LOAD_TILE

    // epilogue: dequant + bias; streaming stores (out never re-read)
    const float iscale = g_scale;
    #pragma unroll
    for (int in_ = 0; in_ < 4; in_++) {
        int col = bn + wn * 32 + in_ * 8 + t4 * 2;
        float s0 = iscale * g_wscale[col];
        float s1 = iscale * g_wscale[col + 1];
        float b0 = bias[col];
        float b1 = bias[col + 1];
        #pragma unroll
        for (int im = 0; im < 4; im++) {
            int row = bm + wm * 64 + im * 16 + g;
            float* c = acc[im][in_];
            float2 v0 = make_float2(c[0] * s0 + b0, c[1] * s1 + b1);
            float2 v1 = make_float2(c[2] * s0 + b0, c[3] * s1 + b1);
            __stcs((float2*)&out[(size_t)row * O_DIM + col],       v0);
            __stcs((float2*)&out[(size_t)(row + 8) * O_DIM + col], v1);
        }
    }
}

// ---------------- launch ----------------
extern "C" void kernel_launch(void* const* d_in, const int* in_sizes, int n_in,
                              void* d_out, int out_size) {
    const float* x    = (const float*)d_in[0];   // [T, 1024]
    const float* w    = (const float*)d_in[1];   // [1024, 1024]
    const float* bias = (const float*)d_in[2];   // [1024]
    float* out = (float*)d_out;                  // [T, 1024] fp32

    const int n  = in_sizes[0];
    const int n4 = n / 4;
    const int n8 = n / 8;
    const int T  = n / K_DIM;                    // 32768

    prep_kernel<<<O_DIM + AMAX_BLOCKS, 256>>>(x, w, n4);
    xq_kernel<<<2048, 256>>>(x, n8);

    cudaFuncSetAttribute(gemm_kernel,
                         cudaFuncAttributeMaxDynamicSharedMemorySize, SMEM_TOTAL);
    dim3 grid(O_DIM / BN, T / BM);               // (8, 256)
    gemm_kernel<<<grid, 256, SMEM_TOTAL>>>(bias, out);
}

// round 14
// speedup vs baseline: 1.0973x; 1.0042x over previous
#include <cuda_runtime.h>
#include <cuda_fp16.h>
#include <cstdint>

#define K_DIM 1024
#define O_DIM 1024
#define FP8_MAX_F 448.0f
#define AMAX_BLOCKS 1184

// ---- GEMM tiling (HMMA mma.sync path; tcgen05 unavailable at compute_103) ----
#define BM 128
#define BN 128
#define BK 64                  // 128 bytes/row fp16 = one SW128 atom
#define STAGES 3
#define NT (K_DIM / BK)        // 16

#define A_STAGE_BYTES (BM * 128)                        // 16384
#define B_STAGE_BYTES (BN * 128)                        // 16384
#define STAGE_BYTES   (A_STAGE_BYTES + B_STAGE_BYTES)   // 32768
#define SMEM_TOTAL    (STAGES * STAGE_BYTES)            // 98304

static __device__ __forceinline__ uint32_t sw128(uint32_t off) {
    return off ^ ((off >> 3) & 0x70);
}
static __device__ __forceinline__ uint32_t smem_u32(const void* p) {
    uint32_t a;
    asm("{ .reg .u64 t; cvta.to.shared.u64 t, %1; cvt.u32.u64 %0, t; }" : "=r"(a) : "l"(p));
    return a;
}

// ---- scratch (static device globals; no runtime allocation) ----
__device__ float  g_partial[AMAX_BLOCKS];   // per-block amax partials (overwritten each launch)
__device__ float  g_scale;                  // final input scale (same value stored by all xq blocks)
__device__ float  g_wscale[O_DIM];
__device__ __half g_wq[(size_t)O_DIM * K_DIM];
__device__ __half g_xq[(size_t)32768 * K_DIM];

// ---------------- kernel 1: fused weight-quant + x-amax partials ----------------
// blocks 0..1023: per-row weight amax + quantize; blocks 1024..2207: x amax partial
__global__ void prep_kernel(const float* __restrict__ x, const float* __restrict__ w, int n4) {
    const int tid = threadIdx.x;
    if (blockIdx.x < O_DIM) {
        // ---- weight row quantization ----
        const int row = blockIdx.x;
        const float* wr = w + (size_t)row * K_DIM;
        float m = 0.f;
        for (int k = tid; k < K_DIM; k += 256) m = fmaxf(m, fabsf(wr[k]));
        #pragma unroll
        for (int o = 16; o; o >>= 1) m = fmaxf(m, __shfl_xor_sync(0xffffffffu, m, o));
        __shared__ float sm[8];
        if ((tid & 31) == 0) sm[tid >> 5] = m;
        __syncthreads();
        float am = sm[0];
        #pragma unroll
        for (int i = 1; i < 8; i++) am = fmaxf(am, sm[i]);
        float scale = fmaxf(__fdiv_rn(am, FP8_MAX_F), 1e-12f);
        if (tid == 0) g_wscale[row] = scale;
        for (int k = tid; k < K_DIM; k += 256) {
            float q = rintf(fminf(fmaxf(__fdiv_rn(wr[k], scale), -FP8_MAX_F), FP8_MAX_F));
            g_wq[(size_t)row * K_DIM + k] = __float2half_rn(q);  // exact (integer <= 448)
        }
    } else {
        // ---- x amax partial: single contiguous stream, plain store (no init/atomics) ----
        const int b = blockIdx.x - O_DIM;
        const float4* x4 = (const float4*)x;
        float m = 0.f;
        const int stride = AMAX_BLOCKS * 256;
        for (int j = b * 256 + tid; j < n4; j += stride) {
            float4 v = x4[j];
            m = fmaxf(m, fmaxf(fmaxf(fabsf(v.x), fabsf(v.y)), fmaxf(fabsf(v.z), fabsf(v.w))));
        }
        #pragma unroll
        for (int o = 16; o; o >>= 1) m = fmaxf(m, __shfl_xor_sync(0xffffffffu, m, o));
        __shared__ float sm2[8];
        if ((tid & 31) == 0) sm2[tid >> 5] = m;
        __syncthreads();
        if (tid == 0) {
            float am = sm2[0];
            #pragma unroll
            for (int i = 1; i < 8; i++) am = fmaxf(am, sm2[i]);
            g_partial[b] = am;
        }
    }
}

// ---------------- kernel 2: quantize x to fp16 (partials reduce + recip-mul) ----------------
__global__ void xq_kernel(const float* __restrict__ x, int n8) {
    const int tid = threadIdx.x;
    // reduce the 1184 partial maxima (identical result in every block)
    float m = 0.f;
    #pragma unroll 5
    for (int i = tid; i < AMAX_BLOCKS; i += 256) m = fmaxf(m, g_partial[i]);
    #pragma unroll
    for (int o = 16; o; o >>= 1) m = fmaxf(m, __shfl_xor_sync(0xffffffffu, m, o));
    __shared__ float sm[8];
    __shared__ float s_inv;
    if ((tid & 31) == 0) sm[tid >> 5] = m;
    __syncthreads();
    if (tid == 0) {
        float am = sm[0];
        #pragma unroll
        for (int i = 1; i < 8; i++) am = fmaxf(am, sm[i]);
        float scale = fmaxf(__fdiv_rn(am, FP8_MAX_F), 1e-12f);
        g_scale = scale;                 // same value from every block: benign
        s_inv = __fdiv_rn(1.0f, scale);
    }
    __syncthreads();
    const float inv = s_inv;

    const float4* x4 = (const float4*)x;
    int stride = gridDim.x * blockDim.x;
    for (int j = blockIdx.x * blockDim.x + tid; j < n8; j += stride) {
        float4 v0 = __ldcs(&x4[j * 2]);      // last use of x: stream, don't pollute L2
        float4 v1 = __ldcs(&x4[j * 2 + 1]);
        float q[8];
        q[0] = v0.x; q[1] = v0.y; q[2] = v0.z; q[3] = v0.w;
        q[4] = v1.x; q[5] = v1.y; q[6] = v1.z; q[7] = v1.w;
        uint4 u;
        uint32_t* up = (uint32_t*)&u;
        #pragma unroll
        for (int p = 0; p < 4; p++) {
            float a = rintf(fminf(fmaxf(q[p * 2]     * inv, -FP8_MAX_F), FP8_MAX_F));
            float b = rintf(fminf(fmaxf(q[p * 2 + 1] * inv, -FP8_MAX_F), FP8_MAX_F));
            __half2 h = __floats2half2_rn(a, b);
            up[p] = *reinterpret_cast<unsigned int*>(&h);
        }
        *reinterpret_cast<uint4*>(&g_xq[(size_t)j * 8]) = u;   // keep cacheable: GEMM re-reads
    }
}

// ---------------- kernel 3: pipelined HMMA GEMM (cp.async + ldmatrix) ----------------
// out[t, o] = acc(t,o) * (g_scale * wscale[o]) + bias[o]
__global__ void __launch_bounds__(256, 2)
gemm_kernel(const float* __restrict__ bias, float* __restrict__ out) {
    extern __shared__ __align__(1024) char smem[];
    const uint32_t smem_base = smem_u32(smem);

    const int tid  = threadIdx.x;
    const int wid  = tid >> 5, lane = tid & 31;
    const int wm   = wid >> 2, wn = wid & 3;      // 2x4 warp grid; warp tile 64x32
    const int g    = lane >> 2, t4 = lane & 3;
    const int bm   = blockIdx.y * BM;
    const int bn   = blockIdx.x * BN;

    const __half* Ag = g_xq + (size_t)bm * K_DIM;
    const __half* Bg = g_wq + (size_t)bn * K_DIM;

#define LOAD_TILE(kt, s) do {                                                          \
    uint32_t sb = smem_base + (s) * STAGE_BYTES;                                       \
    _Pragma("unroll")                                                                  \
    for (int i = 0; i < 4; i++) {                                                      \
        int idx = tid + i * 256;                                                       \
        int r = idx >> 3, c = idx & 7;                                                 \
        const __half* ga = Ag + (size_t)r * K_DIM + (kt) * BK + c * 8;                 \
        uint32_t sa = sb + sw128((uint32_t)(r * 128 + c * 16));                        \
        asm volatile("cp.async.cg.shared.global [%0], [%1], 16;" :: "r"(sa), "l"(ga)); \
    }                                                                                  \
    _Pragma("unroll")                                                                  \
    for (int i = 0; i < 4; i++) {                                                      \
        int idx = tid + i * 256;                                                       \
        int r = idx >> 3, c = idx & 7;                                                 \
        const __half* gb = Bg + (size_t)r * K_DIM + (kt) * BK + c * 8;                 \
        uint32_t sa = sb + A_STAGE_BYTES + sw128((uint32_t)(r * 128 + c * 16));        \
        asm volatile("cp.async.cg.shared.global [%0], [%1], 16;" :: "r"(sa), "l"(gb)); \
    }                                                                                  \
    asm volatile("cp.async.commit_group;" ::: "memory");                               \
} while (0)

    // ldmatrix per-lane constants
    const int rl = (lane & 7) + ((lane >> 3) & 1) * 8;   // row offset 0..15
    const uint32_t cl = (lane >> 4) * 16;                // +16 bytes for upper 8-lane group

    uint32_t rowA[4], xmA[4], rowB[2], xmB[2];
    #pragma unroll
    for (int im = 0; im < 4; im++) {
        rowA[im] = (uint32_t)(wm * 64 + im * 16 + rl) * 128;
        xmA[im]  = (rowA[im] >> 3) & 0x70;
    }
    #pragma unroll
    for (int in2 = 0; in2 < 2; in2++) {
        rowB[in2] = (uint32_t)(wn * 32 + in2 * 16 + rl) * 128 + A_STAGE_BYTES;
        xmB[in2]  = (rowB[in2] >> 3) & 0x70;
    }

    float acc[4][4][4];
    #pragma unroll
    for (int i = 0; i < 4; i++)
        #pragma unroll
        for (int j = 0; j < 4; j++)
            #pragma unroll
            for (int r = 0; r < 4; r++) acc[i][j][r] = 0.f;

    LOAD_TILE(0, 0);
    LOAD_TILE(1, 1);

    for (int kt = 0; kt < NT; kt++) {
        const int s = kt % STAGES;
        if (kt == NT - 1) {
            asm volatile("cp.async.wait_group 0;" ::: "memory");
        } else {
            asm volatile("cp.async.wait_group 1;" ::: "memory");
        }
        // Single barrier per tile: passing it proves all warps finished tile kt-1,
        // so stage (kt+2)%3 == (kt-1)%3 is reusable.
        __syncthreads();

        if (kt + 2 < NT) LOAD_TILE(kt + 2, (kt + 2) % STAGES);

        const uint32_t stage = smem_base + s * STAGE_BYTES;
        #pragma unroll
        for (int kk8 = 0; kk8 < 4; kk8++) {           // k = kk8*16
            const uint32_t colb = (uint32_t)kk8 * 32 + cl;
            uint32_t a[4][4], bf[2][4];
            #pragma unroll
            for (int im = 0; im < 4; im++) {
                uint32_t ad = stage + rowA[im] + (colb ^ xmA[im]);
                asm volatile("ldmatrix.sync.aligned.m8n8.x4.shared.b16 {%0,%1,%2,%3}, [%4];"
                             : "=r"(a[im][0]), "=r"(a[im][1]), "=r"(a[im][2]), "=r"(a[im][3])
                             : "r"(ad));
            }
            #pragma unroll
            for (int in2 = 0; in2 < 2; in2++) {
                uint32_t ad = stage + rowB[in2] + (colb ^ xmB[in2]);
                asm volatile("ldmatrix.sync.aligned.m8n8.x4.shared.b16 {%0,%1,%2,%3}, [%4];"
                             : "=r"(bf[in2][0]), "=r"(bf[in2][1]), "=r"(bf[in2][2]), "=r"(bf[in2][3])
                             : "r"(ad));
            }
            #pragma unroll
            for (int im = 0; im < 4; im++) {
                #pragma unroll
                for (int in_ = 0; in_ < 4; in_++) {
                    uint32_t b0 = (in_ & 1) ? bf[in_ >> 1][1] : bf[in_ >> 1][0];
                    uint32_t b1 = (in_ & 1) ? bf[in_ >> 1][3] : bf[in_ >> 1][2];
                    float* c = acc[im][in_];
                    asm volatile(
                        "mma.sync.aligned.m16n8k16.row.col.f32.f16.f16.f32 "
                        "{%0,%1,%2,%3}, {%4,%5,%6,%7}, {%8,%9}, {%0,%1,%2,%3};\n"
                        : "+f"(c[0]), "+f"(c[1]), "+f"(c[2]), "+f"(c[3])
                        : "r"(a[im][0]), "r"(a[im][1]), "r"(a[im][2]), "r"(a[im][3]),
                          "r"(b0), "r"(b1));
                }
            }
        }
    }
#undef LOAD_TILE

    // epilogue: dequant + bias; streaming stores (out never re-read)
    const float iscale = g_scale;
    #pragma unroll
    for (int in_ = 0; in_ < 4; in_++) {
        int col = bn + wn * 32 + in_ * 8 + t4 * 2;
        float s0 = iscale * g_wscale[col];
        float s1 = iscale * g_wscale[col + 1];
        float b0 = bias[col];
        float b1 = bias[col + 1];
        #pragma unroll
        for (int im = 0; im < 4; im++) {
            int row = bm + wm * 64 + im * 16 + g;
            float* c = acc[im][in_];
            float2 v0 = make_float2(c[0] * s0 + b0, c[1] * s1 + b1);
            float2 v1 = make_float2(c[2] * s0 + b0, c[3] * s1 + b1);
            __stcs((float2*)&out[(size_t)row * O_DIM + col],       v0);
            __stcs((float2*)&out[(size_t)(row + 8) * O_DIM + col], v1);
        }
    }
}

// ---------------- launch ----------------
extern "C" void kernel_launch(void* const* d_in, const int* in_sizes, int n_in,
                              void* d_out, int out_size) {
    const float* x    = (const float*)d_in[0];   // [T, 1024]
    const float* w    = (const float*)d_in[1];   // [1024, 1024]
    const float* bias = (const float*)d_in[2];   // [1024]
    float* out = (float*)d_out;                  // [T, 1024] fp32

    const int n  = in_sizes[0];
    const int n4 = n / 4;
    const int n8 = n / 8;
    const int T  = n / K_DIM;                    // 32768

    prep_kernel<<<O_DIM + AMAX_BLOCKS, 256>>>(x, w, n4);
    xq_kernel<<<2048, 256>>>(x, n8);

    cudaFuncSetAttribute(gemm_kernel,
                         cudaFuncAttributeMaxDynamicSharedMemorySize, SMEM_TOTAL);
    dim3 grid(O_DIM / BN, T / BM);               // (8, 256)
    gemm_kernel<<<grid, 256, SMEM_TOTAL>>>(bias, out);
}